// round 10
// baseline (speedup 1.0000x reference)
#include <cuda_runtime.h>
#include <cuda_bf16.h>

#define BB 2048
#define TT 128
#define DD 512

typedef unsigned long long ull;

// Scratch: gi transposed as [(t*3+g)*B + b]  -> coalesced reads in the scan.
__device__ float g_giT[3 * TT * BB];

__device__ __forceinline__ float tanh_fast(float x) {
    float y;
    asm("tanh.approx.f32 %0, %1;" : "=f"(y) : "f"(x));
    return y;
}

// Packed f32x2 FMA (Blackwell): d = a*b + c elementwise on two floats.
__device__ __forceinline__ ull ffma2(ull a, ull b, ull c) {
    ull d;
    asm("fma.rn.f32x2 %0, %1, %2, %3;" : "=l"(d) : "l"(a), "l"(b), "l"(c));
    return d;
}

__device__ __forceinline__ float pairsum(ull v) {
    float lo, hi;
    asm("mov.b64 {%0, %1}, %2;" : "=f"(lo), "=f"(hi) : "l"(v));
    return lo + hi;
}

// ---------------------------------------------------------------------------
// Kernel A: gi[b,t,g] = sum_d x[b,t,d] * w_ih[g,d]
// One warp per row. FFMA2 packed math (24 instr/row) + 9-shuffle reduction.
// HBM-bound: 512 MB of x read once.
// ---------------------------------------------------------------------------
__global__ void __launch_bounds__(256) gi_kernel(const float* __restrict__ x,
                                                 const float* __restrict__ w_ih) {
    const int lane   = threadIdx.x & 31;
    const int warp   = (blockIdx.x * blockDim.x + threadIdx.x) >> 5;
    const int nwarps = (gridDim.x * blockDim.x) >> 5;

    // Weights as packed f32x2: gate g, pair p -> wp[g*256 + p].
    // Lane covers float4 slots j = lane + 32*i  -> pairs 2j, 2j+1.
    const ull* wp = (const ull*)w_ih;
    ull wr2[8], wz2[8], wn2[8];
#pragma unroll
    for (int i = 0; i < 4; i++) {
        const int j2 = 2 * (lane + 32 * i);
        wr2[2 * i]     = wp[0 * 256 + j2];
        wr2[2 * i + 1] = wp[0 * 256 + j2 + 1];
        wz2[2 * i]     = wp[1 * 256 + j2];
        wz2[2 * i + 1] = wp[1 * 256 + j2 + 1];
        wn2[2 * i]     = wp[2 * 256 + j2];
        wn2[2 * i + 1] = wp[2 * 256 + j2 + 1];
    }

    const int total = BB * TT;
    for (int row = warp; row < total; row += nwarps) {
        const int t = row >> 11;          // row / 2048
        const int b = row & (BB - 1);     // row % 2048
        const longlong2* xr = (const longlong2*)(x + ((size_t)b * TT + t) * DD);

        // Front-batch 4 independent LDG.128 per lane.
        longlong2 v[4];
#pragma unroll
        for (int i = 0; i < 4; i++) v[i] = xr[lane + 32 * i];

        ull ar = 0ull, az = 0ull, an = 0ull;   // packed (0.f, 0.f)
#pragma unroll
        for (int i = 0; i < 4; i++) {
            const ull lo = (ull)v[i].x, hi = (ull)v[i].y;
            ar = ffma2(lo, wr2[2 * i], ar);
            az = ffma2(lo, wz2[2 * i], az);
            an = ffma2(lo, wn2[2 * i], an);
            ar = ffma2(hi, wr2[2 * i + 1], ar);
            az = ffma2(hi, wz2[2 * i + 1], az);
            an = ffma2(hi, wn2[2 * i + 1], an);
        }
        float sr = pairsum(ar), sz = pairsum(az), sn = pairsum(an);

        // Stage 1: bfly {16,8} per gate -> lane holds its 8-group partial.
#pragma unroll
        for (int off = 16; off >= 8; off >>= 1) {
            sr += __shfl_xor_sync(0xffffffffu, sr, off);
            sz += __shfl_xor_sync(0xffffffffu, sz, off);
            sn += __shfl_xor_sync(0xffffffffu, sn, off);
        }
        // Stage 2: route gates to lane octants, 3 shared bfly stages.
        float val = (lane < 8) ? sr : ((lane < 16) ? sz : sn);
#pragma unroll
        for (int off = 4; off >= 1; off >>= 1)
            val += __shfl_xor_sync(0xffffffffu, val, off);

        // Lanes 0, 8, 16 hold full sr, sz, sn. One predicated STG.
        if ((lane & 7) == 0 && lane < 24)
            g_giT[(t * 3 + (lane >> 3)) * BB + b] = val;
    }
}

// ---------------------------------------------------------------------------
// Kernel B: GRU scan (R7 structure — fastest measured).
// Phase 1: all 8 warps stage the block's 48 KB gi tile into smem.
// Phase 2: warp 0 runs the serial scan from smem (1-step register prefetch).
// Phase 3: all 8 warps reduce over b (16 t's per warp) -> atomicAdd.
// ---------------------------------------------------------------------------
__global__ void __launch_bounds__(256) scan_kernel(const float* __restrict__ h0,
                                                   const float* __restrict__ w_hh,
                                                   const float* __restrict__ b_ih,
                                                   const float* __restrict__ b_hh,
                                                   float* __restrict__ out) {
    __shared__ float sg[TT * 3 * 32];               // 48 KB: [(t*3+g)*32 + lane]
    const int tid  = threadIdx.x;
    const int lane = tid & 31;
    const int wid  = tid >> 5;
    const int b0   = blockIdx.x * 32;

    // Phase 1: cooperative tile load (48 rows of 128B per warp).
#pragma unroll 8
    for (int r = wid; r < TT * 3; r += 8)
        sg[r * 32 + lane] = g_giT[(size_t)r * BB + b0 + lane];
    __syncthreads();

    // Phase 2: serial scan by warp 0.
    if (wid == 0) {
        const float whh0h = 0.5f * w_hh[0];
        const float whh1h = 0.5f * w_hh[1];
        const float whh2  = w_hh[2];
        const float c0h   = 0.5f * (b_ih[0] + b_hh[0]);
        const float c1h   = 0.5f * (b_ih[1] + b_hh[1]);
        const float cn    = b_ih[2];
        const float ch2   = b_hh[2];

        float h = h0[b0 + lane];

        float gr = sg[0 * 32 + lane];
        float gz = sg[1 * 32 + lane];
        float gn = sg[2 * 32 + lane];

#pragma unroll
        for (int t = 0; t < TT; t++) {
            // Prefetch next step (off-chain LDS, hidden under the chain).
            float ngr = 0.f, ngz = 0.f, ngn = 0.f;
            if (t + 1 < TT) {
                ngr = sg[((t + 1) * 3 + 0) * 32 + lane];
                ngz = sg[((t + 1) * 3 + 1) * 32 + lane];
                ngn = sg[((t + 1) * 3 + 2) * 32 + lane];
            }

            // Off-chain folds.
            const float grh = fmaf(gr, 0.5f, c0h);
            const float gzh = fmaf(gz, 0.5f, c1h);
            const float gnc = gn + cn;

            // Chain: FFMA -> MUFU(r) -> FFMA -> MUFU(n) -> FFMA (~46 cy).
            const float th_r = tanh_fast(fmaf(h, whh0h, grh));
            const float th_z = tanh_fast(fmaf(h, whh1h, gzh)); // parallel
            const float ghnh = 0.5f * fmaf(h, whh2, ch2);      // parallel
            const float n    = tanh_fast(fmaf(th_r, ghnh, gnc + ghnh));
            const float z    = fmaf(th_z, 0.5f, 0.5f);
            const float zh   = z * h;                          // parallel to n
            const float omz  = fmaf(th_z, -0.5f, 0.5f);        // 1 - z
            h = fmaf(omz, n, zh);

            sg[(t * 3 + 2) * 32 + lane] = h;                   // reuse consumed slot
            gr = ngr; gz = ngz; gn = ngn;
        }
    }
    __syncthreads();

    // Phase 3: reduction over lanes, 16 t's per warp, all warps.
    const float inv = 1.0f / (float)BB;
#pragma unroll
    for (int j = 0; j < 16; j++) {
        const int t = wid * 16 + j;
        float s = sg[(t * 3 + 2) * 32 + lane];
#pragma unroll
        for (int off = 16; off; off >>= 1)
            s += __shfl_down_sync(0xffffffffu, s, off);
        if (lane == 0)
            atomicAdd(out + t, s * inv);
    }
}

// ---------------------------------------------------------------------------
// Launch: inputs per metadata order: x, h0, w_ih, w_hh, b_ih, b_hh
// ---------------------------------------------------------------------------
extern "C" void kernel_launch(void* const* d_in, const int* in_sizes, int n_in,
                              void* d_out, int out_size) {
    const float* x    = (const float*)d_in[0];
    const float* h0   = (const float*)d_in[1];
    const float* w_ih = (const float*)d_in[2];
    const float* w_hh = (const float*)d_in[3];
    const float* b_ih = (const float*)d_in[4];
    const float* b_hh = (const float*)d_in[5];
    float* out = (float*)d_out;

    cudaMemsetAsync(out, 0, (size_t)out_size * sizeof(float));

    gi_kernel<<<4096, 256>>>(x, w_ih);
    scan_kernel<<<BB / 32, 256>>>(h0, w_hh, b_ih, b_hh, out);
}

// round 17
// speedup vs baseline: 1.2287x; 1.2287x over previous
#include <cuda_runtime.h>
#include <cuda_bf16.h>

#define BB 2048
#define TT 128
#define DD 512

// Scratch: gi transposed as [(t*3+g)*B + b]  -> coalesced reads in the scan.
__device__ float g_giT[3 * TT * BB];

__device__ __forceinline__ float tanh_fast(float x) {
    float y;
    asm("tanh.approx.f32 %0, %1;" : "=f"(y) : "f"(x));
    return y;
}

// ---------------------------------------------------------------------------
// Kernel A: gi[b,t,g] = sum_d x[b,t,d] * w_ih[g,d]
// B-MAJOR row order: one warp handles (b, t) and (b, t+1) -> a single
// contiguous 4 KB x read; concurrent warps walk adjacent 4 KB chunks
// (DRAM page-local), unlike the old t-major order whose concurrent reads
// were 256 KB apart. giT stores (24 B/pair) become scattered; write
// overhead ~5% of read traffic -- acceptable.
// ---------------------------------------------------------------------------
__global__ void __launch_bounds__(256) gi_kernel(const float* __restrict__ x,
                                                 const float* __restrict__ w_ih) {
    const int lane   = threadIdx.x & 31;
    const int warp   = (blockIdx.x * blockDim.x + threadIdx.x) >> 5;
    const int nwarps = (gridDim.x * blockDim.x) >> 5;

    float4 wr[4], wz[4], wn[4];
    const float4* w4 = (const float4*)w_ih;
#pragma unroll
    for (int i = 0; i < 4; i++) {
        int j = lane + 32 * i;
        wr[i] = w4[0 * (DD / 4) + j];
        wz[i] = w4[1 * (DD / 4) + j];
        wn[i] = w4[2 * (DD / 4) + j];
    }

    const int npairs = (BB * TT) / 2;
    for (int pair = warp; pair < npairs; pair += nwarps) {
        const int row = pair * 2;                 // b-major: row = b*TT + t
        const int b  = row >> 7;                  // row / 128
        const int t0 = row & (TT - 1);            // even
        const int t1 = t0 + 1;

        // 4 KB contiguous: rows (b,t0) and (b,t1).
        const float4* xr = (const float4*)(x + ((size_t)b * TT + t0) * DD);

        // Front-batch all 8 loads (MLP=8 per lane), covering both rows.
        float4 v0[4], v1[4];
#pragma unroll
        for (int i = 0; i < 4; i++) v0[i] = xr[lane + 32 * i];
#pragma unroll
        for (int i = 0; i < 4; i++) v1[i] = xr[128 + lane + 32 * i];

        float sr0 = 0.f, sz0 = 0.f, sn0 = 0.f;
        float sr1 = 0.f, sz1 = 0.f, sn1 = 0.f;
#pragma unroll
        for (int i = 0; i < 4; i++) {
            sr0 += v0[i].x * wr[i].x + v0[i].y * wr[i].y + v0[i].z * wr[i].z + v0[i].w * wr[i].w;
            sz0 += v0[i].x * wz[i].x + v0[i].y * wz[i].y + v0[i].z * wz[i].z + v0[i].w * wz[i].w;
            sn0 += v0[i].x * wn[i].x + v0[i].y * wn[i].y + v0[i].z * wn[i].z + v0[i].w * wn[i].w;
            sr1 += v1[i].x * wr[i].x + v1[i].y * wr[i].y + v1[i].z * wr[i].z + v1[i].w * wr[i].w;
            sz1 += v1[i].x * wz[i].x + v1[i].y * wz[i].y + v1[i].z * wz[i].z + v1[i].w * wz[i].w;
            sn1 += v1[i].x * wn[i].x + v1[i].y * wn[i].y + v1[i].z * wn[i].z + v1[i].w * wn[i].w;
        }
#pragma unroll
        for (int off = 16; off; off >>= 1) {
            sr0 += __shfl_down_sync(0xffffffffu, sr0, off);
            sz0 += __shfl_down_sync(0xffffffffu, sz0, off);
            sn0 += __shfl_down_sync(0xffffffffu, sn0, off);
            sr1 += __shfl_down_sync(0xffffffffu, sr1, off);
            sz1 += __shfl_down_sync(0xffffffffu, sz1, off);
            sn1 += __shfl_down_sync(0xffffffffu, sn1, off);
        }
        if (lane == 0) {
            g_giT[(t0 * 3 + 0) * BB + b] = sr0;
            g_giT[(t0 * 3 + 1) * BB + b] = sz0;
            g_giT[(t0 * 3 + 2) * BB + b] = sn0;
            g_giT[(t1 * 3 + 0) * BB + b] = sr1;
            g_giT[(t1 * 3 + 1) * BB + b] = sz1;
            g_giT[(t1 * 3 + 2) * BB + b] = sn1;
        }
    }
}

// ---------------------------------------------------------------------------
// Kernel B: GRU scan (proven R10 structure, float4 staging).
// Phase 1: all 8 warps stage the block's 48 KB gi tile into smem as float4
//          (12 independent LDG.128 per thread -> deep MLP).
// Phase 2: warp 0 runs the serial scan from smem (1-step register prefetch).
// Phase 3: all 8 warps reduce over b (16 t's per warp) -> atomicAdd.
// ---------------------------------------------------------------------------
__global__ void __launch_bounds__(256) scan_kernel(const float* __restrict__ h0,
                                                   const float* __restrict__ w_hh,
                                                   const float* __restrict__ b_ih,
                                                   const float* __restrict__ b_hh,
                                                   float* __restrict__ out) {
    __shared__ float sg[TT * 3 * 32];               // 48 KB: [(t*3+g)*32 + lane]
    const int tid  = threadIdx.x;
    const int lane = tid & 31;
    const int wid  = tid >> 5;
    const int b0   = blockIdx.x * 32;

    // Phase 1: float4 cooperative tile load. 384 rows x 8 float4 = 3072 vec4,
    // 12 per thread, all independent.
    {
        float4* sg4 = (float4*)sg;
#pragma unroll
        for (int k = 0; k < 12; k++) {
            const int i = tid + k * 256;            // 0..3071
            const int r = i >> 3;                   // gi row (t*3+g)
            const int q = i & 7;                    // float4 within 32 b's
            sg4[i] = ((const float4*)(g_giT + (size_t)r * BB + b0))[q];
        }
    }
    __syncthreads();

    // Phase 2: serial scan by warp 0.
    if (wid == 0) {
        const float whh0h = 0.5f * w_hh[0];
        const float whh1h = 0.5f * w_hh[1];
        const float whh2  = w_hh[2];
        const float c0h   = 0.5f * (b_ih[0] + b_hh[0]);
        const float c1h   = 0.5f * (b_ih[1] + b_hh[1]);
        const float cn    = b_ih[2];
        const float ch2   = b_hh[2];

        float h = h0[b0 + lane];

        float gr = sg[0 * 32 + lane];
        float gz = sg[1 * 32 + lane];
        float gn = sg[2 * 32 + lane];

#pragma unroll
        for (int t = 0; t < TT; t++) {
            // Prefetch next step (off-chain LDS, hidden under the chain).
            float ngr = 0.f, ngz = 0.f, ngn = 0.f;
            if (t + 1 < TT) {
                ngr = sg[((t + 1) * 3 + 0) * 32 + lane];
                ngz = sg[((t + 1) * 3 + 1) * 32 + lane];
                ngn = sg[((t + 1) * 3 + 2) * 32 + lane];
            }

            // Off-chain folds.
            const float grh = fmaf(gr, 0.5f, c0h);
            const float gzh = fmaf(gz, 0.5f, c1h);
            const float gnc = gn + cn;

            // Chain: FFMA -> MUFU(r) -> FFMA -> MUFU(n) -> FFMA (~46 cy).
            const float th_r = tanh_fast(fmaf(h, whh0h, grh));
            const float th_z = tanh_fast(fmaf(h, whh1h, gzh)); // parallel
            const float ghnh = 0.5f * fmaf(h, whh2, ch2);      // parallel
            const float n    = tanh_fast(fmaf(th_r, ghnh, gnc + ghnh));
            const float z    = fmaf(th_z, 0.5f, 0.5f);
            const float zh   = z * h;                          // parallel to n
            const float omz  = fmaf(th_z, -0.5f, 0.5f);        // 1 - z
            h = fmaf(omz, n, zh);

            sg[(t * 3 + 2) * 32 + lane] = h;                   // reuse consumed slot
            gr = ngr; gz = ngz; gn = ngn;
        }
    }
    __syncthreads();

    // Phase 3: reduction over lanes, 16 t's per warp, all warps.
    const float inv = 1.0f / (float)BB;
#pragma unroll
    for (int j = 0; j < 16; j++) {
        const int t = wid * 16 + j;
        float s = sg[(t * 3 + 2) * 32 + lane];
#pragma unroll
        for (int off = 16; off; off >>= 1)
            s += __shfl_down_sync(0xffffffffu, s, off);
        if (lane == 0)
            atomicAdd(out + t, s * inv);
    }
}

// ---------------------------------------------------------------------------
// Launch: inputs per metadata order: x, h0, w_ih, w_hh, b_ih, b_hh
// ---------------------------------------------------------------------------
extern "C" void kernel_launch(void* const* d_in, const int* in_sizes, int n_in,
                              void* d_out, int out_size) {
    const float* x    = (const float*)d_in[0];
    const float* h0   = (const float*)d_in[1];
    const float* w_ih = (const float*)d_in[2];
    const float* w_hh = (const float*)d_in[3];
    const float* b_ih = (const float*)d_in[4];
    const float* b_hh = (const float*)d_in[5];
    float* out = (float*)d_out;

    cudaMemsetAsync(out, 0, (size_t)out_size * sizeof(float));

    gi_kernel<<<4096, 256>>>(x, w_ih);
    scan_kernel<<<BB / 32, 256>>>(h0, w_hh, b_ih, b_hh, out);
}